// round 2
// baseline (speedup 1.0000x reference)
#include <cuda_runtime.h>
#include <cuda_bf16.h>
#include <cstdint>
#include <cstddef>

#define M_TOTAL 8192
#define IN_F    4096
#define OUT_F   11008
#define BM      128
#define BN      128
#define BK      64
#define NCHUNKS (IN_F / BK)   /* 64 */
#define THREADS 256

/* ---- tcgen05-path smem layout (rows of 128B, SW128) ---- */
#define TC_AHI   0
#define TC_ALO   (BM * 128)           /* 16384 */
#define TC_B     (2 * BM * 128)       /* 32768 */
#define TC_STAGE (3 * BM * 128)       /* 49152 */

/* ---- fallback-path smem layout (rows padded to 72 bf16 = 144B) ---- */
#define FB_STRIDE 144
#define FB_ARR    (BM * FB_STRIDE)    /* 18432 */
#define FB_AHI    0
#define FB_ALO    FB_ARR
#define FB_B      (2 * FB_ARR)
#define FB_STAGE  (3 * FB_ARR)        /* 55296 */

#define SMEM_DATA0 1024
#define SMEM_TOTAL (SMEM_DATA0 + 2 * FB_STAGE)   /* 111616 >= tc needs 99328 */

/* bf16 scratch (alloc-free rule: __device__ globals) */
__device__ __nv_bfloat16 g_xhi[(size_t)M_TOTAL * IN_F];
__device__ __nv_bfloat16 g_xlo[(size_t)M_TOTAL * IN_F];
__device__ __nv_bfloat16 g_w[(size_t)OUT_F * IN_F];

#if defined(__CUDA_ARCH__) && defined(__CUDA_ARCH_FEAT_SM103_ALL)
#define TCPATH 1
#else
#define TCPATH 0
#endif

static __device__ __forceinline__ uint32_t smem_u32(const void* p) {
    uint32_t a;
    asm("{ .reg .u64 t; cvta.to.shared.u64 t, %1; cvt.u32.u64 %0, t; }"
        : "=r"(a) : "l"(p));
    return a;
}

/* =================== tcgen05 helpers (feature-guarded) =================== */
#if TCPATH

/* SW128 smem descriptor: layout=2(SW128), version=1, SBO=64, LBO=1 */
#define DESC_BASE ((2ull << 61) | (1ull << 46) | (64ull << 32) | (1ull << 16))
/* idesc kind::f16: dtype=F32(1<<4), atype=BF16(1<<7), btype=BF16(1<<10),
   N/8=16 (<<17), M/16=8 (<<24) */
#define IDESC 0x8200490u

static __device__ __forceinline__ uint32_t elect_one() {
    uint32_t p;
    asm volatile("{ .reg .pred p; elect.sync _|p, 0xFFFFFFFF; selp.b32 %0, 1, 0, p; }"
                 : "=r"(p));
    return p;
}

static __device__ __forceinline__ void wait_parity(uint32_t bar, int parity) {
    asm volatile(
        "{\n\t"
        ".reg .pred P;\n\t"
        "WAIT%=:\n\t"
        "mbarrier.try_wait.parity.acquire.cta.shared::cta.b64 P, [%0], %1, 0x989680;\n\t"
        "@!P bra WAIT%=;\n\t"
        "}"
        :: "r"(bar), "r"((uint32_t)parity) : "memory");
}

static __device__ __forceinline__ void mma_f16_ss(uint32_t d_tmem, uint64_t adesc,
                                                  uint64_t bdesc, uint32_t enable) {
    asm volatile(
        "{\n\t"
        ".reg .pred p;\n\t"
        "setp.ne.u32 p, %4, 0;\n\t"
        "tcgen05.mma.cta_group::1.kind::f16 [%0], %1, %2, %3, {%5, %5, %5, %5}, p;\n\t"
        "}"
        :: "r"(d_tmem), "l"(adesc), "l"(bdesc), "r"(IDESC), "r"(enable), "r"(0u)
        : "memory");
}

static __device__ __forceinline__ void ldtm_x32(uint32_t* r, uint32_t addr) {
    asm volatile(
        "tcgen05.ld.sync.aligned.32x32b.x32.b32 "
        "{%0, %1, %2, %3, %4, %5, %6, %7, "
        " %8, %9, %10, %11, %12, %13, %14, %15, "
        " %16, %17, %18, %19, %20, %21, %22, %23, "
        " %24, %25, %26, %27, %28, %29, %30, %31}, [%32];"
        : "=r"(r[0]),  "=r"(r[1]),  "=r"(r[2]),  "=r"(r[3]),
          "=r"(r[4]),  "=r"(r[5]),  "=r"(r[6]),  "=r"(r[7]),
          "=r"(r[8]),  "=r"(r[9]),  "=r"(r[10]), "=r"(r[11]),
          "=r"(r[12]), "=r"(r[13]), "=r"(r[14]), "=r"(r[15]),
          "=r"(r[16]), "=r"(r[17]), "=r"(r[18]), "=r"(r[19]),
          "=r"(r[20]), "=r"(r[21]), "=r"(r[22]), "=r"(r[23]),
          "=r"(r[24]), "=r"(r[25]), "=r"(r[26]), "=r"(r[27]),
          "=r"(r[28]), "=r"(r[29]), "=r"(r[30]), "=r"(r[31])
        : "r"(addr));
}
#endif /* TCPATH */

/* =================== fallback (HMMA) helpers — valid on any sm_80+ ===== */

static __device__ __forceinline__ void cp16(uint32_t dst, const void* src) {
    asm volatile("cp.async.cg.shared.global [%0], [%1], 16;"
                 :: "r"(dst), "l"(src) : "memory");
}

static __device__ __forceinline__ void ldm_x4(uint32_t* r, uint32_t a) {
    asm volatile("ldmatrix.sync.aligned.m8n8.x4.shared.b16 {%0,%1,%2,%3}, [%4];"
                 : "=r"(r[0]), "=r"(r[1]), "=r"(r[2]), "=r"(r[3]) : "r"(a));
}

static __device__ __forceinline__ void mma16816(float* d, const uint32_t* a,
                                                const uint32_t* b) {
    asm volatile(
        "mma.sync.aligned.m16n8k16.row.col.f32.bf16.bf16.f32 "
        "{%0,%1,%2,%3}, {%4,%5,%6,%7}, {%8,%9}, {%0,%1,%2,%3};"
        : "+f"(d[0]), "+f"(d[1]), "+f"(d[2]), "+f"(d[3])
        : "r"(a[0]), "r"(a[1]), "r"(a[2]), "r"(a[3]), "r"(b[0]), "r"(b[1]));
}

static __device__ __forceinline__ void fb_prefetch(
    uint32_t st, const __nv_bfloat16* gAh, const __nv_bfloat16* gAl,
    const __nv_bfloat16* gB, long k0, uint32_t dstbase) {
#pragma unroll
    for (int i = 0; i < 4; i++) {
        uint32_t d = dstbase + i * 16;
        cp16(st + FB_AHI + d, gAh + k0 + i * 8);
        cp16(st + FB_ALO + d, gAl + k0 + i * 8);
        cp16(st + FB_B + d, gB + k0 + i * 8);
    }
    asm volatile("cp.async.commit_group;" ::: "memory");
}

/* ---------------- phase 1: conversions ---------------- */

__global__ void k_convert_x(const float* __restrict__ x) {
    const long n4 = (long)M_TOTAL * IN_F / 4;
    const long stride = (long)gridDim.x * blockDim.x;
    for (long i = (long)blockIdx.x * blockDim.x + threadIdx.x; i < n4; i += stride) {
        float4 v = ((const float4*)x)[i];
        float a0 = v.x, a1 = v.y, a2 = v.z, a3 = v.w;
        __nv_bfloat16 h0 = __float2bfloat16(a0);
        __nv_bfloat16 h1 = __float2bfloat16(a1);
        __nv_bfloat16 h2 = __float2bfloat16(a2);
        __nv_bfloat16 h3 = __float2bfloat16(a3);
        __nv_bfloat16 l0 = __float2bfloat16(a0 - __bfloat162float(h0));
        __nv_bfloat16 l1 = __float2bfloat16(a1 - __bfloat162float(h1));
        __nv_bfloat16 l2 = __float2bfloat16(a2 - __bfloat162float(h2));
        __nv_bfloat16 l3 = __float2bfloat16(a3 - __bfloat162float(h3));
        __nv_bfloat162* ph = (__nv_bfloat162*)g_xhi;
        __nv_bfloat162* pl = (__nv_bfloat162*)g_xlo;
        __nv_bfloat162 t;
        t.x = h0; t.y = h1; ph[2 * i]     = t;
        t.x = h2; t.y = h3; ph[2 * i + 1] = t;
        t.x = l0; t.y = l1; pl[2 * i]     = t;
        t.x = l2; t.y = l3; pl[2 * i + 1] = t;
    }
}

__global__ void k_convert_w(const int* __restrict__ wq) {
    const long n4 = (long)OUT_F * IN_F / 4;
    const long stride = (long)gridDim.x * blockDim.x;
    for (long i = (long)blockIdx.x * blockDim.x + threadIdx.x; i < n4; i += stride) {
        int4 w = ((const int4*)wq)[i];
        __nv_bfloat162* pw = (__nv_bfloat162*)g_w;
        __nv_bfloat162 t;
        t.x = __float2bfloat16((float)w.x);
        t.y = __float2bfloat16((float)w.y);
        pw[2 * i] = t;
        t.x = __float2bfloat16((float)w.z);
        t.y = __float2bfloat16((float)w.w);
        pw[2 * i + 1] = t;
    }
}

/* ---------------- phase 2: GEMM (dual-path) ---------------- */

__global__ void __launch_bounds__(THREADS, 1)
gemm_kernel(float* __restrict__ out, const float* __restrict__ ws) {
    extern __shared__ char smem[];
    const int tid = threadIdx.x;
    const int wid = tid >> 5;
    const int lid = tid & 31;
    const int n0 = blockIdx.x * BN;
    const int m0 = blockIdx.y * BM;

#if TCPATH
    /* =============== tcgen05 path =============== */
    const uint32_t smem_base = smem_u32(smem);
    if (wid == 0) {
        asm volatile("tcgen05.alloc.cta_group::1.sync.aligned.shared::cta.b32 [%0], %1;"
                     :: "r"(smem_base), "r"(128) : "memory");
        asm volatile("tcgen05.relinquish_alloc_permit.cta_group::1.sync.aligned;");
    }
    if (tid == 0) {
        asm volatile("mbarrier.init.shared.b64 [%0], 1;" :: "r"(smem_base + 8) : "memory");
        asm volatile("mbarrier.init.shared.b64 [%0], 1;" :: "r"(smem_base + 16) : "memory");
    }
    __syncthreads();
    uint32_t tmem_base;
    asm volatile("ld.shared.b32 %0, [%1];" : "=r"(tmem_base) : "r"(smem_base));

    const int r = tid >> 1, half = tid & 1;
    const __nv_bfloat16* srcAh = g_xhi + (size_t)(m0 + r) * IN_F + half * 32;
    const __nv_bfloat16* srcAl = g_xlo + (size_t)(m0 + r) * IN_F + half * 32;
    const __nv_bfloat16* srcB  = g_w   + (size_t)(n0 + r) * IN_F + half * 32;
    const uint32_t rowbase = (uint32_t)r * 128 + half * 64;

    int ph0 = 0, ph1 = 0;
    for (int c = 0; c < NCHUNKS; c++) {
        const int s = c & 1;
        if (c >= 2) {
            if (s == 0) { wait_parity(smem_base + 8, ph0); ph0 ^= 1; }
            else        { wait_parity(smem_base + 16, ph1); ph1 ^= 1; }
        }
        char* st = smem + SMEM_DATA0 + s * TC_STAGE;
        const long k0 = (long)c * BK;
#pragma unroll
        for (int i = 0; i < 4; i++) {
            uint32_t off = rowbase + i * 16;
            uint32_t sw = off ^ ((off >> 3) & 0x70);
            *(uint4*)(st + TC_AHI + sw) = *(const uint4*)(srcAh + k0 + i * 8);
            *(uint4*)(st + TC_ALO + sw) = *(const uint4*)(srcAl + k0 + i * 8);
            *(uint4*)(st + TC_B   + sw) = *(const uint4*)(srcB  + k0 + i * 8);
        }
        asm volatile("fence.proxy.async.shared::cta;" ::: "memory");
        __syncthreads();

        if (wid == 0 && elect_one()) {
            const uint32_t stu = smem_base + SMEM_DATA0 + s * TC_STAGE;
            const uint64_t dAh = DESC_BASE | ((uint64_t)((stu + TC_AHI) >> 4) & 0x3FFF);
            const uint64_t dAl = DESC_BASE | ((uint64_t)((stu + TC_ALO) >> 4) & 0x3FFF);
            const uint64_t dB  = DESC_BASE | ((uint64_t)((stu + TC_B)   >> 4) & 0x3FFF);
#pragma unroll
            for (int k = 0; k < 4; k++) {
                mma_f16_ss(tmem_base, dAh + k * 2, dB + k * 2,
                           (c > 0 || k > 0) ? 1u : 0u);
                mma_f16_ss(tmem_base, dAl + k * 2, dB + k * 2, 1u);
            }
            asm volatile(
                "tcgen05.commit.cta_group::1.mbarrier::arrive::one.shared::cluster.b64 [%0];"
                :: "r"(smem_base + 8 + 8 * s) : "memory");
        }
    }

    wait_parity(smem_base + 8, ph0);
    wait_parity(smem_base + 16, ph1);
    asm volatile("tcgen05.fence::after_thread_sync;" ::: "memory");

    /* epilogue: warp (wid&3) owns TMEM lanes 32*(wid&3); col half = wid>>2 */
    {
        const int sub = wid & 3;
        const int cb = (wid >> 2) * 64;
        float* orow = out + (size_t)(m0 + sub * 32 + lid) * OUT_F + n0;
#pragma unroll
        for (int h = 0; h < 2; h++) {
            uint32_t rr[32];
            ldtm_x32(rr, tmem_base + cb + h * 32);
            asm volatile("tcgen05.wait::ld.sync.aligned;" ::: "memory");
            const int cbase = cb + h * 32;
#pragma unroll
            for (int j = 0; j < 32; j += 4) {
                float4 v;
                v.x = __uint_as_float(rr[j + 0]) * __ldg(ws + n0 + cbase + j + 0);
                v.y = __uint_as_float(rr[j + 1]) * __ldg(ws + n0 + cbase + j + 1);
                v.z = __uint_as_float(rr[j + 2]) * __ldg(ws + n0 + cbase + j + 2);
                v.w = __uint_as_float(rr[j + 3]) * __ldg(ws + n0 + cbase + j + 3);
                *(float4*)(orow + cbase + j) = v;
            }
        }
    }
    asm volatile("tcgen05.fence::before_thread_sync;" ::: "memory");
    __syncthreads();
    if (wid == 0) {
        asm volatile("tcgen05.dealloc.cta_group::1.sync.aligned.b32 %0, %1;"
                     :: "r"(tmem_base), "r"(128));
    }

#else
    /* =============== fallback: mma.sync bf16 (HMMA) =============== */
    const uint32_t sbase = smem_u32(smem) + SMEM_DATA0;
    const int r = tid >> 1, half = tid & 1;
    const __nv_bfloat16* gAh = g_xhi + (size_t)(m0 + r) * IN_F + half * 32;
    const __nv_bfloat16* gAl = g_xlo + (size_t)(m0 + r) * IN_F + half * 32;
    const __nv_bfloat16* gB  = g_w   + (size_t)(n0 + r) * IN_F + half * 32;
    const uint32_t dstbase = (uint32_t)r * FB_STRIDE + half * 64;

    const int wm = (wid & 3) * 32;
    const int wn = (wid >> 2) * 64;
    const int a_row = (lid & 7) + ((lid >> 3) & 1) * 8;
    const int a_koff = (lid >> 4) * 8;
    const int b_row = (lid & 7) + ((lid >> 4) & 1) * 8;
    const int b_koff = ((lid >> 3) & 1) * 8;

    float acc[2][8][4];
#pragma unroll
    for (int mf = 0; mf < 2; mf++)
#pragma unroll
        for (int nf = 0; nf < 8; nf++)
#pragma unroll
            for (int q = 0; q < 4; q++) acc[mf][nf][q] = 0.0f;

    fb_prefetch(sbase, gAh, gAl, gB, 0, dstbase);

    for (int c = 0; c < NCHUNKS; c++) {
        if (c + 1 < NCHUNKS) {
            fb_prefetch(sbase + ((c + 1) & 1) * FB_STAGE, gAh, gAl, gB,
                        (long)(c + 1) * BK, dstbase);
            asm volatile("cp.async.wait_group 1;" ::: "memory");
        } else {
            asm volatile("cp.async.wait_group 0;" ::: "memory");
        }
        __syncthreads();

        const uint32_t st = sbase + (c & 1) * FB_STAGE;
#pragma unroll
        for (int kk = 0; kk < 4; kk++) {
            const int ke = kk * 16;
            uint32_t ah[2][4], al[2][4], bb[16];
#pragma unroll
            for (int mf = 0; mf < 2; mf++) {
                uint32_t base = st + (wm + 16 * mf + a_row) * FB_STRIDE
                                + (ke + a_koff) * 2;
                ldm_x4(ah[mf], base + FB_AHI);
                ldm_x4(al[mf], base + FB_ALO);
            }
#pragma unroll
            for (int nf4 = 0; nf4 < 4; nf4++) {
                uint32_t addr = st + FB_B + (wn + 16 * nf4 + b_row) * FB_STRIDE
                                + (ke + b_koff) * 2;
                ldm_x4(&bb[nf4 * 4], addr);
            }
#pragma unroll
            for (int mf = 0; mf < 2; mf++)
#pragma unroll
                for (int nf = 0; nf < 8; nf++) {
                    const uint32_t* bp = &bb[(nf >> 1) * 4 + (nf & 1) * 2];
                    mma16816(acc[mf][nf], ah[mf], bp);
                    mma16816(acc[mf][nf], al[mf], bp);
                }
        }
        __syncthreads();
    }

    /* epilogue with per-n scale */
#pragma unroll
    for (int nf = 0; nf < 8; nf++) {
        const int n = n0 + wn + nf * 8 + 2 * (lid & 3);
        const float s0 = __ldg(ws + n);
        const float s1 = __ldg(ws + n + 1);
#pragma unroll
        for (int mf = 0; mf < 2; mf++) {
            const int mrow = m0 + wm + 16 * mf + (lid >> 2);
            float2 v0, v1;
            v0.x = acc[mf][nf][0] * s0;
            v0.y = acc[mf][nf][1] * s1;
            v1.x = acc[mf][nf][2] * s0;
            v1.y = acc[mf][nf][3] * s1;
            *(float2*)(out + (size_t)mrow * OUT_F + n) = v0;
            *(float2*)(out + (size_t)(mrow + 8) * OUT_F + n) = v1;
        }
    }
#endif
}

extern "C" void kernel_launch(void* const* d_in, const int* in_sizes, int n_in,
                              void* d_out, int out_size) {
    const float* x  = (const float*)d_in[0];
    const int*   wq = (const int*)d_in[1];
    const float* ws = (const float*)d_in[2];
    float* out = (float*)d_out;

    cudaFuncSetAttribute(gemm_kernel, cudaFuncAttributeMaxDynamicSharedMemorySize,
                         SMEM_TOTAL);

    k_convert_x<<<4096, 256>>>(x);
    k_convert_w<<<4096, 256>>>(wq);

    dim3 grid(OUT_F / BN, M_TOTAL / BM);   /* 86 x 64 */
    gemm_kernel<<<grid, THREADS, SMEM_TOTAL>>>(out, ws);
}